// round 9
// baseline (speedup 1.0000x reference)
#include <cuda_runtime.h>
#include <math_constants.h>

#define BB 8
#define CC 256
#define HH 128
#define WW 128
#define HW (HH*WW)
#define TOPK 10
#define THRESH 0.5f
#define MARGIN 0.5f
#define EPSV 1e-8f
#define NMAPS 16
#define SBLK 8                     // channel blocks per map
#define SCH 32                     // channels per block
#define JCTAS 8                    // tail CTAs per map
#define JROWS 16                   // rows per tail CTA
#define JPIX (JROWS*WW)            // 2048 pixels per tail CTA
#define PADW 130
#define STG_ROWS 18                // 16 rows + halo
#define T2 256

// scratch (no allocations allowed); counters self-reset -> replay-safe
__device__ float4   g_partial[NMAPS][SBLK][HW/4];   // 8MB block-partial sums
__device__ float    g_part_val[NMAPS][JCTAS][TOPK];
__device__ int      g_part_idx[NMAPS][JCTAS][TOPK];
__device__ float    g_losses[BB];
__device__ unsigned g_samp_cnt[BB];
__device__ unsigned g_done_cnt;

// ---------------------------------------------------------------------------
// Kernel 1: contiguous-read partial-sum stream. 256 CTAs x 256 thr.
// CTA = (map, 32-channel block, pixel half). Each channel iteration reads a
// dense contiguous 32KB sub-span of one 64KB channel plane -> chip-wide the
// in-flight address set is dense (DRAM row-buffer friendly), unlike the old
// 64KB-strided walk (measured stuck at ~4TB/s regardless of warps/MLP).
// Accumulators live in registers (acc[8] float4); no smem traffic.
// ---------------------------------------------------------------------------
__global__ void __launch_bounds__(256) stream_kernel(
    const float* __restrict__ det, const float* __restrict__ loc)
{
    const int bid  = blockIdx.x;        // 0..255
    const int m    = bid >> 4;          // map 0..15 (0..7 det, 8..15 loc)
    const int sub  = bid & 15;
    const int blk  = sub >> 1;          // channel block 0..7
    const int half = sub & 1;           // pixel half
    const int b    = m & 7;
    const int tid  = threadIdx.x;

    const float* src = ((m < 8) ? det : loc)
                       + (size_t)b * CC * HW + (size_t)blk * SCH * HW;
    const float4* s4 = (const float4*)src;
    const int g0 = half * 2048 + tid;   // float4 group; k strides 256

    float4 acc[8];
    #pragma unroll
    for (int k = 0; k < 8; k++) acc[k] = make_float4(0.f, 0.f, 0.f, 0.f);

    #pragma unroll 1
    for (int c = 0; c < SCH; c++) {
        const float4* p = s4 + (size_t)c * (HW / 4) + g0;
        float4 v[8];
        #pragma unroll
        for (int k = 0; k < 8; k++) v[k] = __ldcs(p + k * 256);
        #pragma unroll
        for (int k = 0; k < 8; k++) {
            acc[k].x = fmaf(v[k].x, v[k].x, acc[k].x);
            acc[k].y = fmaf(v[k].y, v[k].y, acc[k].y);
            acc[k].z = fmaf(v[k].z, v[k].z, acc[k].z);
            acc[k].w = fmaf(v[k].w, v[k].w, acc[k].w);
        }
    }
    float4* out4 = &g_partial[m][blk][0];
    #pragma unroll
    for (int k = 0; k < 8; k++) out4[g0 + k * 256] = acc[k];
}

// ---------------------------------------------------------------------------
// Kernel 2: tail. 128 CTAs x 256 thr. Stages intensity by summing the 8
// block-partials per pixel (fixed order -> deterministic; L2-hot 8MB) and
// taking sqrt; then the proven R6 pipeline: branch-free 3x3 maxima,
// hierarchical exact top-10, counter-gated cosine loss + final scalar.
// ---------------------------------------------------------------------------
__global__ void __launch_bounds__(T2) tail_kernel(
    const float* __restrict__ det, const float* __restrict__ loc,
    float* __restrict__ out)
{
    __shared__ float sbuf[5120];                  // 20KB, phase-aliased
    float* rawp   = sbuf;                         // STG_ROWS*PADW = 2340
    float* masked = sbuf + 2560;                  // JPIX = 2048
    float (*df)[CC] = (float(*)[CC])sbuf;         // loss alias
    float (*lf)[CC] = (float(*)[CC])(sbuf + 2560);// loss alias

    __shared__ float s_wval[8][TOPK];
    __shared__ int   s_widx[8][TOPK];
    __shared__ float s_mv[2][JCTAS * TOPK];
    __shared__ int   s_mi[2][JCTAS * TOPK];
    __shared__ float s_dkv[TOPK], s_lkv[TOPK];
    __shared__ int   s_dki[TOPK], s_lki[TOPK];
    __shared__ float s_na[TOPK], s_nb[TOPK], s_ws[8];
    __shared__ unsigned s_flag;

    const int tid  = threadIdx.x;
    const int lane = tid & 31;
    const int w    = tid >> 5;                    // 8 warps
    const int m    = blockIdx.x >> 3;             // map 0..15
    const int j    = blockIdx.x & 7;              // region within map
    const int b    = m & 7;

    // ---- stage intensity rows (16 + halo): sum 8 block-partials, sqrt ------
    for (int i = tid; i < STG_ROWS * PADW; i += T2) rawp[i] = -CUDART_INF_F;
    __syncthreads();
    {
        const float* gp = (const float*)g_partial;   // [(m*8+blk)<<14 | pix]
        const int lo = max(0, j * JROWS - 1);
        const int hi = min(HH - 1, j * JROWS + JROWS);
        const int npx = (hi - lo + 1) * WW;
        const int pixbase = lo << 7;
        for (int i = tid; i < npx; i += T2) {
            int pix = pixbase + i;
            float a = 0.f;
            #pragma unroll
            for (int blk = 0; blk < SBLK; blk++)
                a += __ldcg(&gp[((m * SBLK + blk) << 14) + pix]);
            int rr = (pix >> 7) - (j * JROWS - 1);
            rawp[rr * PADW + (pix & 127) + 1] = sqrtf(a);
        }
    }
    __syncthreads();

    // ---- branch-free 3x3 strict maxima over 2048 local pixels --------------
    for (int p = tid; p < JPIX; p += T2) {
        int yl = p >> 7, x = p & 127;
        const float* c = &rawp[(yl + 1) * PADW + (x + 1)];
        float v = c[0];
        float n0 = fmaxf(fmaxf(c[-PADW - 1], c[-PADW]), c[-PADW + 1]);
        float n1 = fmaxf(c[-1], c[1]);
        float n2 = fmaxf(fmaxf(c[PADW - 1], c[PADW]), c[PADW + 1]);
        float nmax = fmaxf(fmaxf(n0, n1), n2);
        masked[p] = (v > THRESH && v >= nmax) ? v : -CUDART_INF_F;
    }
    __syncthreads();

    // ---- per-warp top-10 over its 256-pixel slice ---------------------------
    {
        const int base = w * 256;
        for (int k = 0; k < TOPK; k++) {
            float bv = -CUDART_INF_F; int bp = 0x7fffffff;
            #pragma unroll
            for (int q = 0; q < 8; q++) {
                int p = base + q * 32 + lane;
                float v = masked[p];
                if (v > bv || (v == bv && p < bp)) { bv = v; bp = p; }
            }
            #pragma unroll
            for (int o = 16; o > 0; o >>= 1) {
                float v2 = __shfl_down_sync(0xffffffffu, bv, o);
                int   p2 = __shfl_down_sync(0xffffffffu, bp, o);
                if (v2 > bv || (v2 == bv && p2 < bp)) { bv = v2; bp = p2; }
            }
            bv = __shfl_sync(0xffffffffu, bv, 0);
            bp = __shfl_sync(0xffffffffu, bp, 0);
            if (lane == 0) {
                s_wval[w][k] = bv;
                s_widx[w][k] = j * JPIX + bp;      // global pixel index
                masked[bp] = -CUDART_INF_F;
            }
            __syncwarp();
        }
    }
    __syncthreads();

    // ---- warp 0 merges 80 -> region top-10 -> g_part ------------------------
    if (w == 0) {
        float* fv = &s_wval[0][0];
        int*   fi = &s_widx[0][0];
        for (int k = 0; k < TOPK; k++) {
            float bv = -CUDART_INF_F; int bi = 0x7fffffff; int bp = -1;
            #pragma unroll
            for (int q = 0; q < 3; q++) {
                int p = q * 32 + lane;
                if (p < 80) {
                    float v = fv[p]; int i = fi[p];
                    if (v > bv || (v == bv && i < bi)) { bv = v; bi = i; bp = p; }
                }
            }
            #pragma unroll
            for (int o = 16; o > 0; o >>= 1) {
                float v2 = __shfl_down_sync(0xffffffffu, bv, o);
                int   i2 = __shfl_down_sync(0xffffffffu, bi, o);
                int   p2 = __shfl_down_sync(0xffffffffu, bp, o);
                if (v2 > bv || (v2 == bv && i2 < bi)) { bv = v2; bi = i2; bp = p2; }
            }
            bp = __shfl_sync(0xffffffffu, bp, 0);
            if (lane == 0) {
                g_part_val[m][j][k] = bv;
                g_part_idx[m][j][k] = bi;
                if (bp >= 0) fv[bp] = -CUDART_INF_F;
            }
            __syncwarp();
        }
    }
    __syncthreads();
    if (tid == 0) {
        __threadfence();
        unsigned old = atomicAdd(&g_samp_cnt[b], 1u);
        if (old == 15u) g_samp_cnt[b] = 0u;        // reset for replay
        s_flag = (old == 15u);
    }
    __syncthreads();
    if (!s_flag) return;   // last of the sample's 16 CTAs computes the loss

    // ---- merge 80 partials per map: warp0 = det(map b), warp1 = loc(8+b) ---
    __threadfence();
    if (w < 2) {
        const int mm = (w == 0) ? b : (8 + b);
        const float* pv = &g_part_val[mm][0][0];
        const int*   pi = &g_part_idx[mm][0][0];
        for (int p = lane; p < 80; p += 32) {
            s_mv[w][p] = __ldcg(&pv[p]);
            s_mi[w][p] = __ldcg(&pi[p]);
        }
        __syncwarp();
        for (int k = 0; k < TOPK; k++) {
            float bv = -CUDART_INF_F; int bi = 0x7fffffff; int bp = -1;
            #pragma unroll
            for (int q = 0; q < 3; q++) {
                int p = q * 32 + lane;
                if (p < 80) {
                    float v = s_mv[w][p]; int i = s_mi[w][p];
                    if (v > bv || (v == bv && i < bi)) { bv = v; bi = i; bp = p; }
                }
            }
            #pragma unroll
            for (int o = 16; o > 0; o >>= 1) {
                float v2 = __shfl_down_sync(0xffffffffu, bv, o);
                int   i2 = __shfl_down_sync(0xffffffffu, bi, o);
                int   p2 = __shfl_down_sync(0xffffffffu, bp, o);
                if (v2 > bv || (v2 == bv && i2 < bi)) { bv = v2; bi = i2; bp = p2; }
            }
            bp = __shfl_sync(0xffffffffu, bp, 0);
            if (lane == 0) {
                if (w == 0) { s_dkv[k] = bv; s_dki[k] = (bv > -CUDART_INF_F) ? bi : 0; }
                else        { s_lkv[k] = bv; s_lki[k] = (bv > -CUDART_INF_F) ? bi : 0; }
                if (bp >= 0) s_mv[w][bp] = -CUDART_INF_F;
            }
            __syncwarp();
        }
    }
    __syncthreads();   // detection smem dead before alias overwrite

    // ---- gather features [10][256] x2 (20 scattered loads/thread) ----------
    {
        const float* dbase = det + (size_t)b * CC * HW;
        const float* lbase = loc + (size_t)b * CC * HW;
        for (int idx = tid; idx < TOPK * CC; idx += T2) {
            int k = idx >> 8, c = idx & 255;
            df[k][c] = __ldg(&dbase[(size_t)c * HW + s_dki[k]]);
            lf[k][c] = __ldg(&lbase[(size_t)c * HW + s_lki[k]]);
        }
    }
    __syncthreads();

    // ---- norms (warp-per-row) ----------------------------------------------
    for (int k = w; k < TOPK; k += 8) {
        float sa = 0.f, sb = 0.f;
        #pragma unroll
        for (int c = lane; c < CC; c += 32) {
            sa = fmaf(df[k][c], df[k][c], sa);
            sb = fmaf(lf[k][c], lf[k][c], sb);
        }
        #pragma unroll
        for (int o = 16; o > 0; o >>= 1) {
            sa += __shfl_down_sync(0xffffffffu, sa, o);
            sb += __shfl_down_sync(0xffffffffu, sb, o);
        }
        if (lane == 0) {
            s_na[k] = fmaxf(sqrtf(sa), EPSV);
            s_nb[k] = fmaxf(sqrtf(sb), EPSV);
        }
    }
    __syncthreads();

    // ---- 100 pair dots over 8 warps ----------------------------------------
    float lsum = 0.f;
    for (int p = w; p < TOPK * TOPK; p += 8) {
        int i = p / TOPK, jj = p % TOPK;
        float dot = 0.f;
        #pragma unroll
        for (int c = lane; c < CC; c += 32) dot = fmaf(df[i][c], lf[jj][c], dot);
        #pragma unroll
        for (int o = 16; o > 0; o >>= 1)
            dot += __shfl_down_sync(0xffffffffu, dot, o);
        if (lane == 0 && s_dkv[i] > -CUDART_INF_F && s_lkv[jj] > -CUDART_INF_F)
            lsum += fmaxf(dot / (s_na[i] * s_nb[jj]) - MARGIN, 0.f);
    }
    if (lane == 0) s_ws[w] = lsum;
    __syncthreads();

    if (tid == 0) {
        int nd = 0, nl = 0;
        #pragma unroll
        for (int k = 0; k < TOPK; k++) {
            nd += (s_dkv[k] > -CUDART_INF_F) ? 1 : 0;
            nl += (s_lkv[k] > -CUDART_INF_F) ? 1 : 0;
        }
        float ssum = 0.f;
        #pragma unroll
        for (int q = 0; q < 8; q++) ssum += s_ws[q];
        int np = nd * nl;
        g_losses[b] = (np > 0) ? (ssum / (float)np) : 0.f;

        // last loss CTA writes the scalar (fixed-order, deterministic)
        __threadfence();
        unsigned old = atomicAdd(&g_done_cnt, 1u);
        if (old == (BB - 1)) {
            g_done_cnt = 0u;   // reset for replay
            __threadfence();
            float tot = 0.f;
            #pragma unroll
            for (int q = 0; q < BB; q++) tot += __ldcg(&g_losses[q]);
            out[0] = tot / (float)BB;
        }
    }
}

extern "C" void kernel_launch(void* const* d_in, const int* in_sizes, int n_in,
                              void* d_out, int out_size)
{
    const float* loc = (const float*)d_in[0];   // loc_features [8,256,128,128]
    const float* det = (const float*)d_in[1];   // det_features [8,256,128,128]
    float* out = (float*)d_out;

    stream_kernel<<<NMAPS * 16, 256>>>(det, loc);
    tail_kernel<<<NMAPS * JCTAS, T2>>>(det, loc, out);
}

// round 10
// speedup vs baseline: 1.0664x; 1.0664x over previous
#include <cuda_runtime.h>
#include <math_constants.h>

#define BB 8
#define CC 256
#define HH 128
#define WW 128
#define HW (HH*WW)
#define TOPK 10
#define THRESH 0.5f
#define MARGIN 0.5f
#define EPSV 1e-8f
#define NMAPS 16
#define NCTA 256                   // total CTAs; ALL co-resident (2/SM needed)
#define JCTAS 8                    // region CTAs per map (CTAs 0..127)
#define JROWS 16
#define JPIX (JROWS*WW)
#define PADW 130
#define STG_ROWS 18
#define NT 256

// scratch (no allocations); all counters self-reset -> graph-replay-safe
__device__ float    g_intensity[NMAPS][HW];
__device__ float    g_part_val[NMAPS][JCTAS][TOPK];
__device__ int      g_part_idx[NMAPS][JCTAS][TOPK];
__device__ float    g_losses[BB];
__device__ unsigned g_samp_cnt[BB];
__device__ unsigned g_done_cnt;
__device__ unsigned g_bar_arrive;
__device__ unsigned g_bar_depart;

__global__ void __launch_bounds__(NT) fused_kernel(
    const float* __restrict__ det, const float* __restrict__ loc,
    float* __restrict__ out)
{
    __shared__ float sbuf[5120];                  // 20KB phase-union
    float* rawp   = sbuf;                         // region: 18*130 = 2340
    float* masked = sbuf + 2560;                  // region: 2048
    float4* s_part = (float4*)sbuf;               // stream: 256 float4 = 4KB
    float (*df)[CC] = (float(*)[CC])sbuf;         // loss alias
    float (*lf)[CC] = (float(*)[CC])(sbuf + 2560);

    __shared__ float s_wval[8][TOPK];
    __shared__ int   s_widx[8][TOPK];
    __shared__ float s_mv[2][JCTAS * TOPK];
    __shared__ int   s_mi[2][JCTAS * TOPK];
    __shared__ float s_dkv[TOPK], s_lkv[TOPK];
    __shared__ int   s_dki[TOPK], s_lki[TOPK];
    __shared__ float s_na[TOPK], s_nb[TOPK], s_ws[8];
    __shared__ unsigned s_flag;

    const int tid  = threadIdx.x;
    const int lane = tid & 31;
    const int w    = tid >> 5;
    const int bid  = blockIdx.x;                  // 0..255

    // ============ Phase A: intensity stream (R8 batch-8 pattern) ============
    {
        const int sm   = bid >> 4;                // map 0..15
        const int sl   = bid & 15;                // slice
        const int sb   = sm & 7;
        const int half = tid >> 7;                // channel half
        const int gl   = tid & 127;
        const int g0   = sl * 256 + gl;           // 2 groups: g0, g0+128
        const float* src = (sm < 8) ? det : loc;
        const float4* base = ((const float4*)(src + (size_t)sb * CC * HW))
                             + (size_t)half * 128 * (HW / 4);
        const float4* p0 = base + g0;
        const float4* p1 = base + g0 + 128;

        float a0=0.f,a1=0.f,a2=0.f,a3=0.f, b0=0.f,b1=0.f,b2=0.f,b3=0.f;
        #pragma unroll 1
        for (int c0 = 0; c0 < 128; c0 += 4) {
            float4 v[8];
            #pragma unroll
            for (int i = 0; i < 4; i++) {
                v[i]     = __ldcs(p0 + (size_t)(c0 + i) * (HW / 4));
                v[4 + i] = __ldcs(p1 + (size_t)(c0 + i) * (HW / 4));
            }
            #pragma unroll
            for (int i = 0; i < 4; i++) {
                a0 = fmaf(v[i].x, v[i].x, a0);
                a1 = fmaf(v[i].y, v[i].y, a1);
                a2 = fmaf(v[i].z, v[i].z, a2);
                a3 = fmaf(v[i].w, v[i].w, a3);
                b0 = fmaf(v[4+i].x, v[4+i].x, b0);
                b1 = fmaf(v[4+i].y, v[4+i].y, b1);
                b2 = fmaf(v[4+i].z, v[4+i].z, b2);
                b3 = fmaf(v[4+i].w, v[4+i].w, b3);
            }
        }
        if (half) {
            s_part[gl]       = make_float4(a0, a1, a2, a3);
            s_part[gl + 128] = make_float4(b0, b1, b2, b3);
        }
        __syncthreads();
        if (!half) {
            float4 pa = s_part[gl], pb = s_part[gl + 128];
            float4 oa, ob;
            oa.x = sqrtf(a0 + pa.x); oa.y = sqrtf(a1 + pa.y);
            oa.z = sqrtf(a2 + pa.z); oa.w = sqrtf(a3 + pa.w);
            ob.x = sqrtf(b0 + pb.x); ob.y = sqrtf(b1 + pb.y);
            ob.z = sqrtf(b2 + pb.z); ob.w = sqrtf(b3 + pb.w);
            ((float4*)g_intensity[sm])[g0]       = oa;
            ((float4*)g_intensity[sm])[g0 + 128] = ob;
        }
        __syncthreads();
    }

    // ============ Grid barrier (all 256 CTAs co-resident; self-resetting) ===
    if (tid == 0) {
        __threadfence();
        atomicAdd(&g_bar_arrive, 1u);
        while (*(volatile unsigned*)&g_bar_arrive < NCTA) __nanosleep(64);
        __threadfence();
        unsigned d = atomicAdd(&g_bar_depart, 1u);
        if (d == NCTA - 1) {           // all CTAs past the spin -> safe reset
            g_bar_depart = 0u;
            *(volatile unsigned*)&g_bar_arrive = 0u;
        }
    }
    __syncthreads();

    if (bid >= NMAPS * JCTAS) return;  // CTAs 128..255 done

    // ============ Phase B: region detection + top-10 (proven R6 code) =======
    const int m = bid >> 3;            // map 0..15
    const int j = bid & 7;             // region
    const int b = m & 7;

    for (int i = tid; i < STG_ROWS * PADW; i += NT) rawp[i] = -CUDART_INF_F;
    __syncthreads();
    {
        const float* gi = g_intensity[m];
        for (int i = tid; i < STG_ROWS * WW; i += NT) {
            int r = i >> 7, x = i & 127;
            int grow = j * JROWS - 1 + r;
            if (grow >= 0 && grow < HH)
                rawp[r * PADW + x + 1] = __ldcg(&gi[(grow << 7) + x]);
        }
    }
    __syncthreads();

    for (int p = tid; p < JPIX; p += NT) {
        int yl = p >> 7, x = p & 127;
        const float* c = &rawp[(yl + 1) * PADW + (x + 1)];
        float v = c[0];
        float n0 = fmaxf(fmaxf(c[-PADW - 1], c[-PADW]), c[-PADW + 1]);
        float n1 = fmaxf(c[-1], c[1]);
        float n2 = fmaxf(fmaxf(c[PADW - 1], c[PADW]), c[PADW + 1]);
        float nmax = fmaxf(fmaxf(n0, n1), n2);
        masked[p] = (v > THRESH && v >= nmax) ? v : -CUDART_INF_F;
    }
    __syncthreads();

    {   // per-warp top-10 over 256-pixel slice
        const int base2 = w * 256;
        for (int k = 0; k < TOPK; k++) {
            float bv = -CUDART_INF_F; int bp = 0x7fffffff;
            #pragma unroll
            for (int q = 0; q < 8; q++) {
                int p = base2 + q * 32 + lane;
                float v = masked[p];
                if (v > bv || (v == bv && p < bp)) { bv = v; bp = p; }
            }
            #pragma unroll
            for (int o = 16; o > 0; o >>= 1) {
                float v2 = __shfl_down_sync(0xffffffffu, bv, o);
                int   p2 = __shfl_down_sync(0xffffffffu, bp, o);
                if (v2 > bv || (v2 == bv && p2 < bp)) { bv = v2; bp = p2; }
            }
            bv = __shfl_sync(0xffffffffu, bv, 0);
            bp = __shfl_sync(0xffffffffu, bp, 0);
            if (lane == 0) {
                s_wval[w][k] = bv;
                s_widx[w][k] = j * JPIX + bp;
                masked[bp] = -CUDART_INF_F;
            }
            __syncwarp();
        }
    }
    __syncthreads();

    if (w == 0) {   // merge 80 -> region top-10
        float* fv = &s_wval[0][0];
        int*   fi = &s_widx[0][0];
        for (int k = 0; k < TOPK; k++) {
            float bv = -CUDART_INF_F; int bi = 0x7fffffff; int bp = -1;
            #pragma unroll
            for (int q = 0; q < 3; q++) {
                int p = q * 32 + lane;
                if (p < 80) {
                    float v = fv[p]; int i = fi[p];
                    if (v > bv || (v == bv && i < bi)) { bv = v; bi = i; bp = p; }
                }
            }
            #pragma unroll
            for (int o = 16; o > 0; o >>= 1) {
                float v2 = __shfl_down_sync(0xffffffffu, bv, o);
                int   i2 = __shfl_down_sync(0xffffffffu, bi, o);
                int   p2 = __shfl_down_sync(0xffffffffu, bp, o);
                if (v2 > bv || (v2 == bv && i2 < bi)) { bv = v2; bi = i2; bp = p2; }
            }
            bp = __shfl_sync(0xffffffffu, bp, 0);
            if (lane == 0) {
                g_part_val[m][j][k] = bv;
                g_part_idx[m][j][k] = bi;
                if (bp >= 0) fv[bp] = -CUDART_INF_F;
            }
            __syncwarp();
        }
    }
    __syncthreads();
    if (tid == 0) {
        __threadfence();
        unsigned old = atomicAdd(&g_samp_cnt[b], 1u);
        if (old == 15u) g_samp_cnt[b] = 0u;
        s_flag = (old == 15u);
    }
    __syncthreads();
    if (!s_flag) return;

    // ============ Phase C: cosine-sim loss for sample b ======================
    __threadfence();
    if (w < 2) {
        const int mm = (w == 0) ? b : (8 + b);
        const float* pv = &g_part_val[mm][0][0];
        const int*   pi = &g_part_idx[mm][0][0];
        for (int p = lane; p < 80; p += 32) {
            s_mv[w][p] = __ldcg(&pv[p]);
            s_mi[w][p] = __ldcg(&pi[p]);
        }
        __syncwarp();
        for (int k = 0; k < TOPK; k++) {
            float bv = -CUDART_INF_F; int bi = 0x7fffffff; int bp = -1;
            #pragma unroll
            for (int q = 0; q < 3; q++) {
                int p = q * 32 + lane;
                if (p < 80) {
                    float v = s_mv[w][p]; int i = s_mi[w][p];
                    if (v > bv || (v == bv && i < bi)) { bv = v; bi = i; bp = p; }
                }
            }
            #pragma unroll
            for (int o = 16; o > 0; o >>= 1) {
                float v2 = __shfl_down_sync(0xffffffffu, bv, o);
                int   i2 = __shfl_down_sync(0xffffffffu, bi, o);
                int   p2 = __shfl_down_sync(0xffffffffu, bp, o);
                if (v2 > bv || (v2 == bv && i2 < bi)) { bv = v2; bi = i2; bp = p2; }
            }
            bp = __shfl_sync(0xffffffffu, bp, 0);
            if (lane == 0) {
                if (w == 0) { s_dkv[k] = bv; s_dki[k] = (bv > -CUDART_INF_F) ? bi : 0; }
                else        { s_lkv[k] = bv; s_lki[k] = (bv > -CUDART_INF_F) ? bi : 0; }
                if (bp >= 0) s_mv[w][bp] = -CUDART_INF_F;
            }
            __syncwarp();
        }
    }
    __syncthreads();

    {
        const float* dbase = det + (size_t)b * CC * HW;
        const float* lbase = loc + (size_t)b * CC * HW;
        for (int idx = tid; idx < TOPK * CC; idx += NT) {
            int k = idx >> 8, c = idx & 255;
            df[k][c] = __ldg(&dbase[(size_t)c * HW + s_dki[k]]);
            lf[k][c] = __ldg(&lbase[(size_t)c * HW + s_lki[k]]);
        }
    }
    __syncthreads();

    for (int k = w; k < TOPK; k += 8) {
        float sa = 0.f, sb = 0.f;
        #pragma unroll
        for (int c = lane; c < CC; c += 32) {
            sa = fmaf(df[k][c], df[k][c], sa);
            sb = fmaf(lf[k][c], lf[k][c], sb);
        }
        #pragma unroll
        for (int o = 16; o > 0; o >>= 1) {
            sa += __shfl_down_sync(0xffffffffu, sa, o);
            sb += __shfl_down_sync(0xffffffffu, sb, o);
        }
        if (lane == 0) {
            s_na[k] = fmaxf(sqrtf(sa), EPSV);
            s_nb[k] = fmaxf(sqrtf(sb), EPSV);
        }
    }
    __syncthreads();

    float lsum = 0.f;
    for (int p = w; p < TOPK * TOPK; p += 8) {
        int i = p / TOPK, jj = p % TOPK;
        float dot = 0.f;
        #pragma unroll
        for (int c = lane; c < CC; c += 32) dot = fmaf(df[i][c], lf[jj][c], dot);
        #pragma unroll
        for (int o = 16; o > 0; o >>= 1)
            dot += __shfl_down_sync(0xffffffffu, dot, o);
        if (lane == 0 && s_dkv[i] > -CUDART_INF_F && s_lkv[jj] > -CUDART_INF_F)
            lsum += fmaxf(dot / (s_na[i] * s_nb[jj]) - MARGIN, 0.f);
    }
    if (lane == 0) s_ws[w] = lsum;
    __syncthreads();

    if (tid == 0) {
        int nd = 0, nl = 0;
        #pragma unroll
        for (int k = 0; k < TOPK; k++) {
            nd += (s_dkv[k] > -CUDART_INF_F) ? 1 : 0;
            nl += (s_lkv[k] > -CUDART_INF_F) ? 1 : 0;
        }
        float ssum = 0.f;
        #pragma unroll
        for (int q = 0; q < 8; q++) ssum += s_ws[q];
        int np = nd * nl;
        g_losses[b] = (np > 0) ? (ssum / (float)np) : 0.f;

        __threadfence();
        unsigned old = atomicAdd(&g_done_cnt, 1u);
        if (old == (BB - 1)) {
            g_done_cnt = 0u;
            __threadfence();
            float tot = 0.f;
            #pragma unroll
            for (int q = 0; q < BB; q++) tot += __ldcg(&g_losses[q]);
            out[0] = tot / (float)BB;
        }
    }
}

extern "C" void kernel_launch(void* const* d_in, const int* in_sizes, int n_in,
                              void* d_out, int out_size)
{
    const float* loc = (const float*)d_in[0];   // loc_features [8,256,128,128]
    const float* det = (const float*)d_in[1];   // det_features [8,256,128,128]
    float* out = (float*)d_out;

    fused_kernel<<<NCTA, NT>>>(det, loc, out);
}

// round 11
// speedup vs baseline: 1.1906x; 1.1164x over previous
#include <cuda_runtime.h>
#include <math_constants.h>

#define BB 8
#define CC 256
#define HH 128
#define WW 128
#define HW (HH*WW)
#define TOPK 10
#define THRESH 0.5f
#define MARGIN 0.5f
#define EPSV 1e-8f
#define NMAPS 16
#define JCTAS 8                    // tail CTAs per map
#define JROWS 16                   // rows per tail CTA
#define JPIX (JROWS*WW)            // 2048 pixels per tail CTA
#define PADW 130
#define STG_ROWS 18                // 16 rows + halo
#define T2 256

// scratch (no allocations allowed); counters self-reset -> replay-safe
__device__ float    g_intensity[NMAPS][HW];
__device__ float    g_part_val[NMAPS][JCTAS][TOPK];
__device__ int      g_part_idx[NMAPS][JCTAS][TOPK];
__device__ float    g_losses[BB];
__device__ unsigned g_samp_cnt[BB];
__device__ unsigned g_done_cnt;

// ---------------------------------------------------------------------------
// Kernel 1: intensity stream. IDENTICAL to R8 except __launch_bounds__(256,2):
// without min-blocks, ptxas targeted 8-CTA occupancy -> 32-reg cap -> the
// 8-deep float4 batch (32 regs of data) was silently serialized to ~2 in
// flight -> ~14KB in flight/SM -> ~3.5TB/s (matches every measured round).
// min_blocks=2 allows 128 regs; grid is 3.46 CTA/SM (grid-limited) so the
// occupancy cost is zero and true MLP=8 gives ~56KB in flight -> DRAM-bound.
// ---------------------------------------------------------------------------
__global__ void __launch_bounds__(256, 2) intensity_kernel(
    const float* __restrict__ det, const float* __restrict__ loc)
{
    __shared__ float4 s_part[128];

    const int bid  = blockIdx.x;
    const int m    = bid >> 5;
    const int sl   = bid & 31;
    const int b    = m & 7;
    const int tid  = threadIdx.x;
    const int half = tid >> 7;
    const int gl   = tid & 127;
    const int g    = sl * 128 + gl;

    const float* src = (m < 8) ? det : loc;
    const float4* base = ((const float4*)(src + (size_t)b * CC * HW))
                         + g + (size_t)half * 128 * (HW / 4);

    float a0 = 0.f, a1 = 0.f, a2 = 0.f, a3 = 0.f;
    #pragma unroll 1
    for (int c0 = 0; c0 < 128; c0 += 8) {
        float4 v[8];
        #pragma unroll
        for (int i = 0; i < 8; i++)
            v[i] = __ldcs(base + (size_t)(c0 + i) * (HW / 4));
        #pragma unroll
        for (int i = 0; i < 8; i++) {
            a0 = fmaf(v[i].x, v[i].x, a0);
            a1 = fmaf(v[i].y, v[i].y, a1);
            a2 = fmaf(v[i].z, v[i].z, a2);
            a3 = fmaf(v[i].w, v[i].w, a3);
        }
    }
    if (half) s_part[gl] = make_float4(a0, a1, a2, a3);
    __syncthreads();
    if (!half) {
        float4 p = s_part[gl];
        float4 o;
        o.x = sqrtf(a0 + p.x);
        o.y = sqrtf(a1 + p.y);
        o.z = sqrtf(a2 + p.z);
        o.w = sqrtf(a3 + p.w);
        ((float4*)g_intensity[m])[g] = o;
    }
}

// ---------------------------------------------------------------------------
// Kernel 2: tail (R6/R8 proven code; launch_bounds(256,2) so the loss-phase
// scattered gathers also get MLP headroom). 128 CTAs x 256 thr.
// ---------------------------------------------------------------------------
__global__ void __launch_bounds__(T2, 2) tail_kernel(
    const float* __restrict__ det, const float* __restrict__ loc,
    float* __restrict__ out)
{
    __shared__ float sbuf[5120];                  // 20KB, phase-aliased
    float* rawp   = sbuf;                         // STG_ROWS*PADW = 2340
    float* masked = sbuf + 2560;                  // JPIX = 2048
    float (*df)[CC] = (float(*)[CC])sbuf;         // loss alias
    float (*lf)[CC] = (float(*)[CC])(sbuf + 2560);// loss alias

    __shared__ float s_wval[8][TOPK];
    __shared__ int   s_widx[8][TOPK];
    __shared__ float s_mv[2][JCTAS * TOPK];
    __shared__ int   s_mi[2][JCTAS * TOPK];
    __shared__ float s_dkv[TOPK], s_lkv[TOPK];
    __shared__ int   s_dki[TOPK], s_lki[TOPK];
    __shared__ float s_na[TOPK], s_nb[TOPK], s_ws[8];
    __shared__ unsigned s_flag;

    const int tid  = threadIdx.x;
    const int lane = tid & 31;
    const int w    = tid >> 5;                    // 8 warps
    const int m    = blockIdx.x >> 3;             // map 0..15
    const int j    = blockIdx.x & 7;              // region within map
    const int b    = m & 7;

    // ---- stage 16 rows + halo into padded smem (-inf border) ---------------
    for (int i = tid; i < STG_ROWS * PADW; i += T2) rawp[i] = -CUDART_INF_F;
    __syncthreads();
    {
        const float* gi = g_intensity[m];
        for (int i = tid; i < STG_ROWS * WW; i += T2) {
            int r = i >> 7, x = i & 127;
            int grow = j * JROWS - 1 + r;
            if (grow >= 0 && grow < HH)
                rawp[r * PADW + x + 1] = __ldcg(&gi[(grow << 7) + x]);
        }
    }
    __syncthreads();

    // ---- branch-free 3x3 strict maxima over 2048 local pixels --------------
    for (int p = tid; p < JPIX; p += T2) {
        int yl = p >> 7, x = p & 127;
        const float* c = &rawp[(yl + 1) * PADW + (x + 1)];
        float v = c[0];
        float n0 = fmaxf(fmaxf(c[-PADW - 1], c[-PADW]), c[-PADW + 1]);
        float n1 = fmaxf(c[-1], c[1]);
        float n2 = fmaxf(fmaxf(c[PADW - 1], c[PADW]), c[PADW + 1]);
        float nmax = fmaxf(fmaxf(n0, n1), n2);
        masked[p] = (v > THRESH && v >= nmax) ? v : -CUDART_INF_F;
    }
    __syncthreads();

    // ---- per-warp top-10 over its 256-pixel slice ---------------------------
    {
        const int base = w * 256;
        for (int k = 0; k < TOPK; k++) {
            float bv = -CUDART_INF_F; int bp = 0x7fffffff;
            #pragma unroll
            for (int q = 0; q < 8; q++) {
                int p = base + q * 32 + lane;
                float v = masked[p];
                if (v > bv || (v == bv && p < bp)) { bv = v; bp = p; }
            }
            #pragma unroll
            for (int o = 16; o > 0; o >>= 1) {
                float v2 = __shfl_down_sync(0xffffffffu, bv, o);
                int   p2 = __shfl_down_sync(0xffffffffu, bp, o);
                if (v2 > bv || (v2 == bv && p2 < bp)) { bv = v2; bp = p2; }
            }
            bv = __shfl_sync(0xffffffffu, bv, 0);
            bp = __shfl_sync(0xffffffffu, bp, 0);
            if (lane == 0) {
                s_wval[w][k] = bv;
                s_widx[w][k] = j * JPIX + bp;      // global pixel index
                masked[bp] = -CUDART_INF_F;
            }
            __syncwarp();
        }
    }
    __syncthreads();

    // ---- warp 0 merges 80 -> region top-10 -> g_part ------------------------
    if (w == 0) {
        float* fv = &s_wval[0][0];
        int*   fi = &s_widx[0][0];
        for (int k = 0; k < TOPK; k++) {
            float bv = -CUDART_INF_F; int bi = 0x7fffffff; int bp = -1;
            #pragma unroll
            for (int q = 0; q < 3; q++) {
                int p = q * 32 + lane;
                if (p < 80) {
                    float v = fv[p]; int i = fi[p];
                    if (v > bv || (v == bv && i < bi)) { bv = v; bi = i; bp = p; }
                }
            }
            #pragma unroll
            for (int o = 16; o > 0; o >>= 1) {
                float v2 = __shfl_down_sync(0xffffffffu, bv, o);
                int   i2 = __shfl_down_sync(0xffffffffu, bi, o);
                int   p2 = __shfl_down_sync(0xffffffffu, bp, o);
                if (v2 > bv || (v2 == bv && i2 < bi)) { bv = v2; bi = i2; bp = p2; }
            }
            bp = __shfl_sync(0xffffffffu, bp, 0);
            if (lane == 0) {
                g_part_val[m][j][k] = bv;
                g_part_idx[m][j][k] = bi;
                if (bp >= 0) fv[bp] = -CUDART_INF_F;
            }
            __syncwarp();
        }
    }
    __syncthreads();
    if (tid == 0) {
        __threadfence();
        unsigned old = atomicAdd(&g_samp_cnt[b], 1u);
        if (old == 15u) g_samp_cnt[b] = 0u;        // reset for replay
        s_flag = (old == 15u);
    }
    __syncthreads();
    if (!s_flag) return;   // last of the sample's 16 CTAs computes the loss

    // ---- merge 80 partials per map: warp0 = det(map b), warp1 = loc(8+b) ---
    __threadfence();
    if (w < 2) {
        const int mm = (w == 0) ? b : (8 + b);
        const float* pv = &g_part_val[mm][0][0];
        const int*   pi = &g_part_idx[mm][0][0];
        for (int p = lane; p < 80; p += 32) {
            s_mv[w][p] = __ldcg(&pv[p]);
            s_mi[w][p] = __ldcg(&pi[p]);
        }
        __syncwarp();
        for (int k = 0; k < TOPK; k++) {
            float bv = -CUDART_INF_F; int bi = 0x7fffffff; int bp = -1;
            #pragma unroll
            for (int q = 0; q < 3; q++) {
                int p = q * 32 + lane;
                if (p < 80) {
                    float v = s_mv[w][p]; int i = s_mi[w][p];
                    if (v > bv || (v == bv && i < bi)) { bv = v; bi = i; bp = p; }
                }
            }
            #pragma unroll
            for (int o = 16; o > 0; o >>= 1) {
                float v2 = __shfl_down_sync(0xffffffffu, bv, o);
                int   i2 = __shfl_down_sync(0xffffffffu, bi, o);
                int   p2 = __shfl_down_sync(0xffffffffu, bp, o);
                if (v2 > bv || (v2 == bv && i2 < bi)) { bv = v2; bi = i2; bp = p2; }
            }
            bp = __shfl_sync(0xffffffffu, bp, 0);
            if (lane == 0) {
                if (w == 0) { s_dkv[k] = bv; s_dki[k] = (bv > -CUDART_INF_F) ? bi : 0; }
                else        { s_lkv[k] = bv; s_lki[k] = (bv > -CUDART_INF_F) ? bi : 0; }
                if (bp >= 0) s_mv[w][bp] = -CUDART_INF_F;
            }
            __syncwarp();
        }
    }
    __syncthreads();   // detection smem dead before alias overwrite

    // ---- gather features [10][256] x2 (20 scattered loads/thread) ----------
    {
        const float* dbase = det + (size_t)b * CC * HW;
        const float* lbase = loc + (size_t)b * CC * HW;
        for (int idx = tid; idx < TOPK * CC; idx += T2) {
            int k = idx >> 8, c = idx & 255;
            df[k][c] = __ldg(&dbase[(size_t)c * HW + s_dki[k]]);
            lf[k][c] = __ldg(&lbase[(size_t)c * HW + s_lki[k]]);
        }
    }
    __syncthreads();

    // ---- norms (warp-per-row) ----------------------------------------------
    for (int k = w; k < TOPK; k += 8) {
        float sa = 0.f, sb = 0.f;
        #pragma unroll
        for (int c = lane; c < CC; c += 32) {
            sa = fmaf(df[k][c], df[k][c], sa);
            sb = fmaf(lf[k][c], lf[k][c], sb);
        }
        #pragma unroll
        for (int o = 16; o > 0; o >>= 1) {
            sa += __shfl_down_sync(0xffffffffu, sa, o);
            sb += __shfl_down_sync(0xffffffffu, sb, o);
        }
        if (lane == 0) {
            s_na[k] = fmaxf(sqrtf(sa), EPSV);
            s_nb[k] = fmaxf(sqrtf(sb), EPSV);
        }
    }
    __syncthreads();

    // ---- 100 pair dots over 8 warps ----------------------------------------
    float lsum = 0.f;
    for (int p = w; p < TOPK * TOPK; p += 8) {
        int i = p / TOPK, jj = p % TOPK;
        float dot = 0.f;
        #pragma unroll
        for (int c = lane; c < CC; c += 32) dot = fmaf(df[i][c], lf[jj][c], dot);
        #pragma unroll
        for (int o = 16; o > 0; o >>= 1)
            dot += __shfl_down_sync(0xffffffffu, dot, o);
        if (lane == 0 && s_dkv[i] > -CUDART_INF_F && s_lkv[jj] > -CUDART_INF_F)
            lsum += fmaxf(dot / (s_na[i] * s_nb[jj]) - MARGIN, 0.f);
    }
    if (lane == 0) s_ws[w] = lsum;
    __syncthreads();

    if (tid == 0) {
        int nd = 0, nl = 0;
        #pragma unroll
        for (int k = 0; k < TOPK; k++) {
            nd += (s_dkv[k] > -CUDART_INF_F) ? 1 : 0;
            nl += (s_lkv[k] > -CUDART_INF_F) ? 1 : 0;
        }
        float ssum = 0.f;
        #pragma unroll
        for (int q = 0; q < 8; q++) ssum += s_ws[q];
        int np = nd * nl;
        g_losses[b] = (np > 0) ? (ssum / (float)np) : 0.f;

        // last loss CTA writes the scalar (fixed-order, deterministic)
        __threadfence();
        unsigned old = atomicAdd(&g_done_cnt, 1u);
        if (old == (BB - 1)) {
            g_done_cnt = 0u;   // reset for replay
            __threadfence();
            float tot = 0.f;
            #pragma unroll
            for (int q = 0; q < BB; q++) tot += __ldcg(&g_losses[q]);
            out[0] = tot / (float)BB;
        }
    }
}

extern "C" void kernel_launch(void* const* d_in, const int* in_sizes, int n_in,
                              void* d_out, int out_size)
{
    const float* loc = (const float*)d_in[0];   // loc_features [8,256,128,128]
    const float* det = (const float*)d_in[1];   // det_features [8,256,128,128]
    float* out = (float*)d_out;

    intensity_kernel<<<512, 256>>>(det, loc);
    tail_kernel<<<NMAPS * JCTAS, T2>>>(det, loc, out);
}